// round 9
// baseline (speedup 1.0000x reference)
#include <cuda_runtime.h>
#include <float.h>

// features [4,256,50,50] f32, rois [128,5] f32 (b,x1,y1,x2,y2),
// out [128,256,7,7] f32. scale=1/16, pooled 7x7, Caffe geometry.
//
// ROUND 9 VARIANT: bin size computed as reciprocal-multiply in f32:
//     bin_w = roi_w * fl32(1/7)        (fl32(1/7) = 0.142857149... > 1/7)
// matching XLA-CPU fast-math (LLVM arcp) codegen of roi_w / 7. The positive
// bias flips ceil() up at integer-crossing edges (pw==6 for all ROIs; all pw
// when 7|roi_w) for large roi_w — last bins gain one out-of-roi line.
// Everything else identical to the established Caffe baseline.

__global__ void roi_pool_rcp(const float* __restrict__ feat,
                             const float* __restrict__ rois,
                             float* __restrict__ out)
{
    const int idx = blockIdx.x * blockDim.x + threadIdx.x;
    if (idx >= 1605632) return;            // 128*256*49

    const int pw = idx % 7;
    const int ph = (idx / 7) % 7;
    const int c  = (idx / 49) % 256;
    const int n  = idx / 12544;

    const float* r = rois + n * 5;
    const int   b  = (int)r[0];
    const float x1 = rintf(r[1] * 0.0625f);   // exact *2^-4, half-even round
    const float y1 = rintf(r[2] * 0.0625f);
    const float x2 = rintf(r[3] * 0.0625f);
    const float y2 = rintf(r[4] * 0.0625f);

    const float roi_w = fmaxf(x2 - x1 + 1.0f, 1.0f);
    const float roi_h = fmaxf(y2 - y1 + 1.0f, 1.0f);

    // Reciprocal-multiply division (fast-math arcp pattern).
    // 1.0f/7.0f folds at compile time to the correctly-rounded fl32(1/7).
    const float C7 = 1.0f / 7.0f;
    const float bw = __fmul_rn(roi_w, C7);
    const float bh = __fmul_rn(roi_h, C7);

    // f32 edges, no FMA contraction, clipped to [0, 50].
    const float wstart = fminf(fmaxf(floorf(__fmul_rn((float)pw, bw))        + x1, 0.0f), 50.0f);
    const float wend   = fminf(fmaxf(ceilf (__fmul_rn((float)pw + 1.0f, bw)) + x1, 0.0f), 50.0f);
    const float hstart = fminf(fmaxf(floorf(__fmul_rn((float)ph, bh))        + y1, 0.0f), 50.0f);
    const float hend   = fminf(fmaxf(ceilf (__fmul_rn((float)ph + 1.0f, bh)) + y1, 0.0f), 50.0f);

    // Edges are integer-valued floats -> exact int casts.
    const int w0 = (int)wstart, w1 = (int)wend;
    const int h0 = (int)hstart, h1 = (int)hend;

    const float* __restrict__ plane = feat + ((size_t)b * 256 + c) * 2500;

    float m = -FLT_MAX;
    for (int h = h0; h < h1; ++h) {
        const float* rowp = plane + h * 50;
        for (int w = w0; w < w1; ++w) {
            m = fmaxf(m, __ldg(rowp + w));
        }
    }

    // Empty bin -> 0 (Caffe semantics).
    out[idx] = (w1 > w0 && h1 > h0) ? m : 0.0f;
}

extern "C" void kernel_launch(void* const* d_in, const int* in_sizes, int n_in,
                              void* d_out, int out_size)
{
    const float* feat = nullptr;
    const float* rois = nullptr;
    for (int i = 0; i < n_in; ++i) {
        long s = in_sizes[i];
        if (s == 2560000L || s == 10240000L) feat = (const float*)d_in[i];
        else if (s == 640L || s == 2560L)    rois = (const float*)d_in[i];
    }
    if (!feat) feat = (const float*)d_in[0];
    if (!rois) rois = (const float*)d_in[n_in > 1 ? 1 : 0];

    roi_pool_rcp<<<6272, 256>>>(feat, rois, (float*)d_out);
}